// round 10
// baseline (speedup 1.0000x reference)
#include <cuda_runtime.h>

#define A 128
#define S 512
#define D 768
#define V 30522
#define NL 10
#define LW 5
#define MASK_ID 103

#define NCH 8          // attention s-chunks per row
#define CHUNK 64
#define JT 12          // dense j tiles (64 each)
#define KT 12          // dense k splits (128 each)
#define NTILE 64

// ---------------- scratch (device globals; no allocs allowed) ---------------
__device__ float g_m[A * NCH];
__device__ float g_l[A * NCH];
__device__ float g_acc[A * NCH * D];
__device__ float g_x[A * 2 * D];          // [att | mask_logit]
__device__ float g_hpart[KT * A * D];
__device__ float g_h[A * D];

// ---------------- kernel 1: fused prep + pipelined online attention ---------
// Depth-2 software pipeline: next row's loads issue before current row's
// reduce/exp/rescale chain, overlapping DRAM latency with compute.
__global__ void __launch_bounds__(256, 2) attn_fused(const float* __restrict__ bert,
                                                     const int* __restrict__ ids,
                                                     const int* __restrict__ length,
                                                     const float* __restrict__ Wsen,
                                                     const float* __restrict__ bsen,
                                                     float* __restrict__ out) {
    int c = blockIdx.x, a = blockIdx.y, tid = threadIdx.x;
    int warp = tid >> 5, lane = tid & 31;
    int len = length[a];
    int s_lo = max(3, c * CHUNK);
    int s_hi = min((c + 1) * CHUNK, 3 + len);
    int idxc = a * NCH + c;
    if (s_lo >= s_hi) {
        if (tid == 0) { g_m[idxc] = -1e30f; g_l[idxc] = 0.f; }
        return;
    }

    __shared__ int mp;
    __shared__ __align__(16) float mls[D];
    __shared__ __align__(16) float pacc[8][D];
    __shared__ float pm[8], pl[8];
    __shared__ float red0[8], red1[8];

    if (tid == 0) mp = S;
    __syncthreads();
    #pragma unroll
    for (int s = tid; s < S; s += 256)
        if (ids[a * S + s] == MASK_ID) atomicMin(&mp, s);
    __syncthreads();

    const float* mlrow = bert + ((size_t)a * S + mp) * D;
    for (int d = tid; d < D; d += 256) mls[d] = mlrow[d];
    __syncthreads();

    if (c == 0) {
        for (int d = tid; d < D; d += 256)
            g_x[a * 2 * D + D + d] = mls[d];
        const float* r0 = bert + (size_t)a * S * D;
        float p0 = 0.f, p1 = 0.f;
        for (int d = tid; d < D; d += 256) {
            float v = r0[d];
            p0 = fmaf(v, Wsen[d], p0);
            p1 = fmaf(v, Wsen[D + d], p1);
        }
        #pragma unroll
        for (int off = 16; off; off >>= 1) {
            p0 += __shfl_xor_sync(0xffffffffu, p0, off);
            p1 += __shfl_xor_sync(0xffffffffu, p1, off);
        }
        if (lane == 0) { red0[warp] = p0; red1[warp] = p1; }
        __syncthreads();
        if (tid == 0) {
            float s0 = 0.f, s1 = 0.f;
            #pragma unroll
            for (int i = 0; i < 8; i++) { s0 += red0[i]; s1 += red1[i]; }
            out[a * 2 + 0] = s0 + bsen[0];
            out[a * 2 + 1] = s1 + bsen[1];
        }
    }

    const float4* ml4 = (const float4*)mls;

    float m_run = -1e30f, l_run = 0.f;
    float acc[24];
    #pragma unroll
    for (int i = 0; i < 24; i++) acc[i] = 0.f;

    int s = s_lo + warp;
    float4 vc[6], vn[6];
    if (s < s_hi) {
        const float4* r = (const float4*)(bert + ((size_t)a * S + s) * D);
        #pragma unroll
        for (int k = 0; k < 6; k++) vc[k] = r[lane + 32 * k];
    }
    for (; s < s_hi; s += 8) {
        int sn = s + 8;
        if (sn < s_hi) {                    // prefetch next row FIRST
            const float4* r = (const float4*)(bert + ((size_t)a * S + sn) * D);
            #pragma unroll
            for (int k = 0; k < 6; k++) vn[k] = r[lane + 32 * k];
        }
        // score of current row against mask_logit (smem)
        float sc = 0.f;
        #pragma unroll
        for (int k = 0; k < 6; k++) {
            float4 u = ml4[lane + 32 * k];
            sc = fmaf(vc[k].x, u.x, sc); sc = fmaf(vc[k].y, u.y, sc);
            sc = fmaf(vc[k].z, u.z, sc); sc = fmaf(vc[k].w, u.w, sc);
        }
        #pragma unroll
        for (int off = 16; off; off >>= 1)
            sc += __shfl_xor_sync(0xffffffffu, sc, off);

        float m_new = fmaxf(m_run, sc);
        float f = __expf(m_run - m_new);
        float e = __expf(sc - m_new);
        l_run = fmaf(l_run, f, e);
        #pragma unroll
        for (int k = 0; k < 6; k++) {
            acc[4*k+0] = fmaf(e, vc[k].x, acc[4*k+0] * f);
            acc[4*k+1] = fmaf(e, vc[k].y, acc[4*k+1] * f);
            acc[4*k+2] = fmaf(e, vc[k].z, acc[4*k+2] * f);
            acc[4*k+3] = fmaf(e, vc[k].w, acc[4*k+3] * f);
        }
        m_run = m_new;
        #pragma unroll
        for (int k = 0; k < 6; k++) vc[k] = vn[k];
    }

    float4* pa = (float4*)pacc[warp];
    #pragma unroll
    for (int k = 0; k < 6; k++)
        pa[lane + 32 * k] = make_float4(acc[4*k], acc[4*k+1], acc[4*k+2], acc[4*k+3]);
    if (lane == 0) { pm[warp] = m_run; pl[warp] = l_run; }
    __syncthreads();

    float M = pm[0];
    #pragma unroll
    for (int w = 1; w < 8; w++) M = fmaxf(M, pm[w]);
    float scale[8]; float L = 0.f;
    #pragma unroll
    for (int w = 0; w < 8; w++) {
        scale[w] = __expf(pm[w] - M);
        L = fmaf(pl[w], scale[w], L);
    }
    size_t ob = (size_t)idxc * D;
    for (int d = tid; d < D; d += 256) {
        float vsum = 0.f;
        #pragma unroll
        for (int w = 0; w < 8; w++)
            vsum = fmaf(pacc[w][d], scale[w], vsum);
        g_acc[ob + d] = vsum;
    }
    if (tid == 0) { g_m[idxc] = M; g_l[idxc] = L; }
}

// ---------------- kernel 2: combine partial softmax, write att into x -------
__global__ void attn_combine() {
    int a = blockIdx.x, tid = threadIdx.x;
    __shared__ float sscale[NCH];
    __shared__ float sLinv;
    if (tid == 0) {
        float M = -1e30f;
        #pragma unroll
        for (int c = 0; c < NCH; c++) M = fmaxf(M, g_m[a * NCH + c]);
        float L = 0.f;
        #pragma unroll
        for (int c = 0; c < NCH; c++) {
            float lc = g_l[a * NCH + c];
            float s = (lc > 0.f) ? expf(g_m[a * NCH + c] - M) : 0.f;
            sscale[c] = s;
            L += lc * s;
        }
        sLinv = 1.f / L;
    }
    __syncthreads();
    float inv = sLinv;
    for (int d = tid; d < D; d += 256) {
        float v = 0.f;
        #pragma unroll
        for (int c = 0; c < NCH; c++)
            v = fmaf(g_acc[(size_t)(a * NCH + c) * D + d], sscale[c], v);
        g_x[a * 2 * D + d] = v * inv;
    }
}

// ---------------- kernel 3: dense GEMM split-K partials (KT=12) -------------
__global__ void dense_partial(const float* __restrict__ Wd) {
    int jt = blockIdx.x;   // 0..11 -> j tile of 64
    int kt = blockIdx.y;   // 0..11 -> k slice of 128
    int tid = threadIdx.x;
    int j0 = jt * NTILE, k0 = kt * 128;
    __shared__ float xs[128][32];
    __shared__ float wst[32][NTILE + 1];
    int tj = tid & 31, tg = tid >> 5;
    float c0[16], c1[16];
    #pragma unroll
    for (int i = 0; i < 16; i++) { c0[i] = 0.f; c1[i] = 0.f; }

    for (int kk = 0; kk < 4; kk++) {
        __syncthreads();
        int kb = k0 + kk * 32;
        #pragma unroll
        for (int i = 0; i < 16; i++) {
            int idx = tid + i * 256;
            int aa = idx >> 5, k = idx & 31;
            xs[aa][k] = g_x[(size_t)aa * (2 * D) + kb + k];
        }
        #pragma unroll
        for (int i = 0; i < 8; i++) {
            int idx = tid + i * 256;
            int j = idx >> 5, k = idx & 31;
            wst[k][j] = Wd[(size_t)(j0 + j) * (2 * D) + kb + k];
        }
        __syncthreads();
        #pragma unroll
        for (int k = 0; k < 32; k++) {
            float w0 = wst[k][tj], w1 = wst[k][tj + 32];
            #pragma unroll
            for (int i = 0; i < 16; i++) {
                float xv = xs[tg + 8 * i][k];
                c0[i] = fmaf(xv, w0, c0[i]);
                c1[i] = fmaf(xv, w1, c1[i]);
            }
        }
    }
    size_t base = (size_t)kt * A * D;
    #pragma unroll
    for (int i = 0; i < 16; i++) {
        int aa = tg + 8 * i;
        g_hpart[base + (size_t)aa * D + j0 + tj] = c0[i];
        g_hpart[base + (size_t)aa * D + j0 + 32 + tj] = c1[i];
    }
}

// ---------------- kernel 4: split-K reduce (4 slices x 3), bias, tanh -------
__global__ void __launch_bounds__(256) dense_finish(const float* __restrict__ bd) {
    __shared__ float4 red[256];
    int e = threadIdx.x & 63, sl = threadIdx.x >> 6;   // 4 slices
    int i4 = blockIdx.x * 64 + e;                      // < A*D/4 = 24576
    float4 s = make_float4(0.f, 0.f, 0.f, 0.f);
    #pragma unroll
    for (int t = sl * 3; t < sl * 3 + 3; t++) {
        float4 v = *(const float4*)(g_hpart + (size_t)t * A * D + (size_t)i4 * 4);
        s.x += v.x; s.y += v.y; s.z += v.z; s.w += v.w;
    }
    red[threadIdx.x] = s;
    __syncthreads();
    if (sl == 0) {
        float4 b = *(const float4*)(bd + (i4 * 4) % D);
        float4 s0 = red[e], s1 = red[e + 64], s2 = red[e + 128], s3 = red[e + 192];
        float4 r;
        r.x = tanhf(b.x + s0.x + s1.x + s2.x + s3.x);
        r.y = tanhf(b.y + s0.y + s1.y + s2.y + s3.y);
        r.z = tanhf(b.z + s0.z + s1.z + s2.z + s3.z);
        r.w = tanhf(b.w + s0.w + s1.w + s2.w + s3.w);
        *(float4*)(g_h + (size_t)i4 * 4) = r;
    }
}

// ---------------- kernel 5: gathered vocab head + label einsum --------------
__global__ void head_kernel(const float* __restrict__ Wp,
                            const float* __restrict__ bp,
                            const int* __restrict__ lwords,
                            const float* __restrict__ Wlab,
                            float* __restrict__ out) {
    int a = blockIdx.x, tid = threadIdx.x;
    __shared__ __align__(16) float hs[D];
    __shared__ float lp[NL * LW];
    for (int d = tid; d < D; d += 256) hs[d] = g_h[a * D + d];
    __syncthreads();
    int warp = tid >> 5, lane = tid & 31;
    const float4* h4 = (const float4*)hs;
    for (int t = warp; t < NL * LW; t += 8) {
        int word = lwords[t];
        const float4* wr = (const float4*)(Wp + (size_t)word * D);
        float acc = 0.f;
        #pragma unroll
        for (int k = 0; k < 6; k++) {
            float4 v = wr[lane + 32 * k];
            float4 u = h4[lane + 32 * k];
            acc = fmaf(v.x, u.x, acc); acc = fmaf(v.y, u.y, acc);
            acc = fmaf(v.z, u.z, acc); acc = fmaf(v.w, u.w, acc);
        }
        #pragma unroll
        for (int off = 16; off; off >>= 1)
            acc += __shfl_xor_sync(0xffffffffu, acc, off);
        if (lane == 0) lp[t] = tanhf(acc + bp[word]);
    }
    __syncthreads();
    if (tid < 2 * NL) {
        int k = tid / NL, l = tid % NL;
        float o = 0.f;
        #pragma unroll
        for (int w = 0; w < LW; w++)
            o = fmaf(lp[l * LW + w], Wlab[(l * 2 + k) * LW + w], o);
        out[2 * A + a * (2 * NL) + k * NL + l] = o;
    }
}

// ---------------------------------------------------------------------------
extern "C" void kernel_launch(void* const* d_in, const int* in_sizes, int n_in,
                              void* d_out, int out_size) {
    const float* bert   = (const float*)d_in[0];
    const int*   ids    = (const int*)d_in[1];
    const int*   length = (const int*)d_in[2];
    const int*   lwords = (const int*)d_in[3];
    const float* Wsen   = (const float*)d_in[4];
    const float* bsen   = (const float*)d_in[5];
    const float* Wd     = (const float*)d_in[6];
    const float* bd     = (const float*)d_in[7];
    const float* Wp     = (const float*)d_in[8];
    const float* bp     = (const float*)d_in[9];
    const float* Wlab   = (const float*)d_in[10];
    float* out = (float*)d_out;

    attn_fused<<<dim3(NCH, A), 256>>>(bert, ids, length, Wsen, bsen, out);
    attn_combine<<<A, 256>>>();
    dense_partial<<<dim3(JT, KT), 256>>>(Wd);
    dense_finish<<<(A * D / 4) / 64, 256>>>(bd);
    head_kernel<<<A, 256>>>(Wp, bp, lwords, Wlab, out);
}

// round 11
// speedup vs baseline: 1.1706x; 1.1706x over previous
#include <cuda_runtime.h>

#define A 128
#define S 512
#define D 768
#define V 30522
#define NL 10
#define LW 5
#define MASK_ID 103

#define NCH 8          // attention s-chunks per row
#define CHUNK 64
#define JT 12          // dense j tiles (64 each)
#define KT 12          // dense k splits (128 each)
#define NTILE 64

// ---------------- scratch (device globals; no allocs allowed) ---------------
__device__ float g_m[A * NCH];
__device__ float g_l[A * NCH];
__device__ float g_acc[A * NCH * D];
__device__ float g_x[A * 2 * D];          // [att | mask_logit]
__device__ float g_hpart[KT * A * D];

// ---------------- kernel 1: fused prep + pipelined online attention ---------
__global__ void __launch_bounds__(256, 2) attn_fused(const float* __restrict__ bert,
                                                     const int* __restrict__ ids,
                                                     const int* __restrict__ length,
                                                     const float* __restrict__ Wsen,
                                                     const float* __restrict__ bsen,
                                                     float* __restrict__ out) {
    int c = blockIdx.x, a = blockIdx.y, tid = threadIdx.x;
    int warp = tid >> 5, lane = tid & 31;
    int len = length[a];
    int s_lo = max(3, c * CHUNK);
    int s_hi = min((c + 1) * CHUNK, 3 + len);
    int idxc = a * NCH + c;
    if (s_lo >= s_hi) {
        if (tid == 0) { g_m[idxc] = -1e30f; g_l[idxc] = 0.f; }
        return;
    }

    __shared__ int mp;
    __shared__ __align__(16) float mls[D];
    __shared__ __align__(16) float pacc[8][D];
    __shared__ float pm[8], pl[8];
    __shared__ float red0[8], red1[8];

    if (tid == 0) mp = S;
    __syncthreads();
    #pragma unroll
    for (int s = tid; s < S; s += 256)
        if (ids[a * S + s] == MASK_ID) atomicMin(&mp, s);
    __syncthreads();

    const float* mlrow = bert + ((size_t)a * S + mp) * D;
    for (int d = tid; d < D; d += 256) mls[d] = mlrow[d];
    __syncthreads();

    if (c == 0) {
        for (int d = tid; d < D; d += 256)
            g_x[a * 2 * D + D + d] = mls[d];
        const float* r0 = bert + (size_t)a * S * D;
        float p0 = 0.f, p1 = 0.f;
        for (int d = tid; d < D; d += 256) {
            float v = r0[d];
            p0 = fmaf(v, Wsen[d], p0);
            p1 = fmaf(v, Wsen[D + d], p1);
        }
        #pragma unroll
        for (int off = 16; off; off >>= 1) {
            p0 += __shfl_xor_sync(0xffffffffu, p0, off);
            p1 += __shfl_xor_sync(0xffffffffu, p1, off);
        }
        if (lane == 0) { red0[warp] = p0; red1[warp] = p1; }
        __syncthreads();
        if (tid == 0) {
            float s0 = 0.f, s1 = 0.f;
            #pragma unroll
            for (int i = 0; i < 8; i++) { s0 += red0[i]; s1 += red1[i]; }
            out[a * 2 + 0] = s0 + bsen[0];
            out[a * 2 + 1] = s1 + bsen[1];
        }
    }

    const float4* ml4 = (const float4*)mls;

    float m_run = -1e30f, l_run = 0.f;
    float acc[24];
    #pragma unroll
    for (int i = 0; i < 24; i++) acc[i] = 0.f;

    int s = s_lo + warp;
    float4 vc[6], vn[6];
    if (s < s_hi) {
        const float4* r = (const float4*)(bert + ((size_t)a * S + s) * D);
        #pragma unroll
        for (int k = 0; k < 6; k++) vc[k] = r[lane + 32 * k];
    }
    for (; s < s_hi; s += 8) {
        int sn = s + 8;
        if (sn < s_hi) {                    // prefetch next row FIRST
            const float4* r = (const float4*)(bert + ((size_t)a * S + sn) * D);
            #pragma unroll
            for (int k = 0; k < 6; k++) vn[k] = r[lane + 32 * k];
        }
        float sc = 0.f;
        #pragma unroll
        for (int k = 0; k < 6; k++) {
            float4 u = ml4[lane + 32 * k];
            sc = fmaf(vc[k].x, u.x, sc); sc = fmaf(vc[k].y, u.y, sc);
            sc = fmaf(vc[k].z, u.z, sc); sc = fmaf(vc[k].w, u.w, sc);
        }
        #pragma unroll
        for (int off = 16; off; off >>= 1)
            sc += __shfl_xor_sync(0xffffffffu, sc, off);

        float m_new = fmaxf(m_run, sc);
        float f = __expf(m_run - m_new);
        float e = __expf(sc - m_new);
        l_run = fmaf(l_run, f, e);
        #pragma unroll
        for (int k = 0; k < 6; k++) {
            acc[4*k+0] = fmaf(e, vc[k].x, acc[4*k+0] * f);
            acc[4*k+1] = fmaf(e, vc[k].y, acc[4*k+1] * f);
            acc[4*k+2] = fmaf(e, vc[k].z, acc[4*k+2] * f);
            acc[4*k+3] = fmaf(e, vc[k].w, acc[4*k+3] * f);
        }
        m_run = m_new;
        #pragma unroll
        for (int k = 0; k < 6; k++) vc[k] = vn[k];
    }

    float4* pa = (float4*)pacc[warp];
    #pragma unroll
    for (int k = 0; k < 6; k++)
        pa[lane + 32 * k] = make_float4(acc[4*k], acc[4*k+1], acc[4*k+2], acc[4*k+3]);
    if (lane == 0) { pm[warp] = m_run; pl[warp] = l_run; }
    __syncthreads();

    float M = pm[0];
    #pragma unroll
    for (int w = 1; w < 8; w++) M = fmaxf(M, pm[w]);
    float scale[8]; float L = 0.f;
    #pragma unroll
    for (int w = 0; w < 8; w++) {
        scale[w] = __expf(pm[w] - M);
        L = fmaf(pl[w], scale[w], L);
    }
    size_t ob = (size_t)idxc * D;
    for (int d = tid; d < D; d += 256) {
        float vsum = 0.f;
        #pragma unroll
        for (int w = 0; w < 8; w++)
            vsum = fmaf(pacc[w][d], scale[w], vsum);
        g_acc[ob + d] = vsum;
    }
    if (tid == 0) { g_m[idxc] = M; g_l[idxc] = L; }
}

// ---------------- kernel 2: combine partial softmax, write att into x -------
__global__ void attn_combine() {
    int a = blockIdx.x, tid = threadIdx.x;
    __shared__ float sscale[NCH];
    __shared__ float sLinv;
    if (tid == 0) {
        float M = -1e30f;
        #pragma unroll
        for (int c = 0; c < NCH; c++) M = fmaxf(M, g_m[a * NCH + c]);
        float L = 0.f;
        #pragma unroll
        for (int c = 0; c < NCH; c++) {
            float lc = g_l[a * NCH + c];
            float s = (lc > 0.f) ? expf(g_m[a * NCH + c] - M) : 0.f;
            sscale[c] = s;
            L += lc * s;
        }
        sLinv = 1.f / L;
    }
    __syncthreads();
    float inv = sLinv;
    for (int d = tid; d < D; d += 256) {
        float v = 0.f;
        #pragma unroll
        for (int c = 0; c < NCH; c++)
            v = fmaf(g_acc[(size_t)(a * NCH + c) * D + d], sscale[c], v);
        g_x[a * 2 * D + d] = v * inv;
    }
}

// ---------------- kernel 3: dense GEMM split-K partials (KT=12) -------------
__global__ void dense_partial(const float* __restrict__ Wd) {
    int jt = blockIdx.x;   // 0..11 -> j tile of 64
    int kt = blockIdx.y;   // 0..11 -> k slice of 128
    int tid = threadIdx.x;
    int j0 = jt * NTILE, k0 = kt * 128;
    __shared__ float xs[128][32];
    __shared__ float wst[32][NTILE + 1];
    int tj = tid & 31, tg = tid >> 5;
    float c0[16], c1[16];
    #pragma unroll
    for (int i = 0; i < 16; i++) { c0[i] = 0.f; c1[i] = 0.f; }

    for (int kk = 0; kk < 4; kk++) {
        __syncthreads();
        int kb = k0 + kk * 32;
        #pragma unroll
        for (int i = 0; i < 16; i++) {
            int idx = tid + i * 256;
            int aa = idx >> 5, k = idx & 31;
            xs[aa][k] = g_x[(size_t)aa * (2 * D) + kb + k];
        }
        #pragma unroll
        for (int i = 0; i < 8; i++) {
            int idx = tid + i * 256;
            int j = idx >> 5, k = idx & 31;
            wst[k][j] = Wd[(size_t)(j0 + j) * (2 * D) + kb + k];
        }
        __syncthreads();
        #pragma unroll
        for (int k = 0; k < 32; k++) {
            float w0 = wst[k][tj], w1 = wst[k][tj + 32];
            #pragma unroll
            for (int i = 0; i < 16; i++) {
                float xv = xs[tg + 8 * i][k];
                c0[i] = fmaf(xv, w0, c0[i]);
                c1[i] = fmaf(xv, w1, c1[i]);
            }
        }
    }
    size_t base = (size_t)kt * A * D;
    #pragma unroll
    for (int i = 0; i < 16; i++) {
        int aa = tg + 8 * i;
        g_hpart[base + (size_t)aa * D + j0 + tj] = c0[i];
        g_hpart[base + (size_t)aa * D + j0 + 32 + tj] = c1[i];
    }
}

// ---------------- kernel 4: fused split-K reduce + tanh + vocab head --------
// One CTA per row a, 768 threads.
// Phase A: reduce 12 partials (thread: d4 = tid%192, slice group tid/192 of 3)
// Phase B: 24 warps do the 50 gathered vocab dots + label einsum.
__global__ void __launch_bounds__(768) tail_kernel(const float* __restrict__ bd,
                                                   const float* __restrict__ Wp,
                                                   const float* __restrict__ bp,
                                                   const int* __restrict__ lwords,
                                                   const float* __restrict__ Wlab,
                                                   float* __restrict__ out) {
    int a = blockIdx.x, tid = threadIdx.x;
    __shared__ __align__(16) float hs[D];
    __shared__ float4 redsm[768];
    __shared__ float lp[NL * LW];

    int q = tid % 192;          // float4 index within the 768-wide row
    int g = tid / 192;          // slice group 0..3 (3 slices each)

    float4 s = make_float4(0.f, 0.f, 0.f, 0.f);
    #pragma unroll
    for (int t = g * 3; t < g * 3 + 3; t++) {
        float4 v = *(const float4*)(g_hpart + (size_t)t * A * D + (size_t)a * D + q * 4);
        s.x += v.x; s.y += v.y; s.z += v.z; s.w += v.w;
    }
    redsm[tid] = s;
    __syncthreads();
    if (g == 0) {
        float4 b = *(const float4*)(bd + q * 4);
        float4 s1 = redsm[q + 192], s2 = redsm[q + 384], s3 = redsm[q + 576];
        float4 r;
        r.x = tanhf(b.x + s.x + s1.x + s2.x + s3.x);
        r.y = tanhf(b.y + s.y + s1.y + s2.y + s3.y);
        r.z = tanhf(b.z + s.z + s1.z + s2.z + s3.z);
        r.w = tanhf(b.w + s.w + s1.w + s2.w + s3.w);
        *(float4*)(hs + q * 4) = r;
    }
    __syncthreads();

    int warp = tid >> 5, lane = tid & 31;   // 24 warps
    const float4* h4 = (const float4*)hs;
    for (int t = warp; t < NL * LW; t += 24) {
        int word = lwords[t];
        const float4* wr = (const float4*)(Wp + (size_t)word * D);
        float acc = 0.f;
        #pragma unroll
        for (int k = 0; k < 6; k++) {
            float4 v = wr[lane + 32 * k];
            float4 u = h4[lane + 32 * k];
            acc = fmaf(v.x, u.x, acc); acc = fmaf(v.y, u.y, acc);
            acc = fmaf(v.z, u.z, acc); acc = fmaf(v.w, u.w, acc);
        }
        #pragma unroll
        for (int off = 16; off; off >>= 1)
            acc += __shfl_xor_sync(0xffffffffu, acc, off);
        if (lane == 0) lp[t] = tanhf(acc + bp[word]);
    }
    __syncthreads();
    if (tid < 2 * NL) {
        int k = tid / NL, l = tid % NL;
        float o = 0.f;
        #pragma unroll
        for (int w = 0; w < LW; w++)
            o = fmaf(lp[l * LW + w], Wlab[(l * 2 + k) * LW + w], o);
        out[2 * A + a * (2 * NL) + k * NL + l] = o;
    }
}

// ---------------------------------------------------------------------------
extern "C" void kernel_launch(void* const* d_in, const int* in_sizes, int n_in,
                              void* d_out, int out_size) {
    const float* bert   = (const float*)d_in[0];
    const int*   ids    = (const int*)d_in[1];
    const int*   length = (const int*)d_in[2];
    const int*   lwords = (const int*)d_in[3];
    const float* Wsen   = (const float*)d_in[4];
    const float* bsen   = (const float*)d_in[5];
    const float* Wd     = (const float*)d_in[6];
    const float* bd     = (const float*)d_in[7];
    const float* Wp     = (const float*)d_in[8];
    const float* bp     = (const float*)d_in[9];
    const float* Wlab   = (const float*)d_in[10];
    float* out = (float*)d_out;

    attn_fused<<<dim3(NCH, A), 256>>>(bert, ids, length, Wsen, bsen, out);
    attn_combine<<<A, 256>>>();
    dense_partial<<<dim3(JT, KT), 256>>>(Wd);
    tail_kernel<<<A, 768>>>(bd, Wp, bp, lwords, Wlab, out);
}